// round 12
// baseline (speedup 1.0000x reference)
#include <cuda_runtime.h>
#include <math.h>

namespace {
constexpr int Bn = 8, Cn = 4, Hn = 256, Wn = 256;
constexpr int NPIX = Bn * Hn * Wn;      // 524288
constexpr int TPB = 128;                // 1 row/block, 2 px/thread
constexpr int NBLK = Bn * Hn;           // 2048
}

__device__ double g_acc;      // zero-init at module load; self-reset each run
__device__ unsigned g_count;

__device__ __forceinline__ int deep_vdist(const int* __restrict__ mask, int base,
                                          int h, int w, int c, int is64) {
    int g0 = 512;
    const int lim_u = h, lim_d = Hn - 1 - h;
    const int lim = (lim_u > lim_d) ? lim_u : lim_d;
    bool done = false;
#pragma unroll 1
    for (int kb = 5; kb <= lim && !done; kb += 4) {
        int uu[4], dd[4];
#pragma unroll
        for (int j = 0; j < 4; ++j) {
            int k = kb + j;
            int hu = (k <= lim_u) ? h - k : h;
            int hd = (k <= lim_d) ? h + k : h;
            uu[j] = __ldg(mask + ((base + hu * Wn + w) << is64));
            dd[j] = __ldg(mask + ((base + hd * Wn + w) << is64));
        }
#pragma unroll
        for (int j = 0; j < 4; ++j)
            if (!done && (uu[j] != c || dd[j] != c)) { g0 = kb + j; done = true; }
    }
    return g0;
}

// Exact lower envelope on packed (cls<<20|g0^2); body runs only when m > 1.
__device__ __forceinline__ float envelope(const int* __restrict__ sp, int w,
                                          int c, float m) {
#pragma unroll 1
    for (int r = 1; r < Wn; ++r) {
        float r2 = (float)(r * r);
        if (r2 >= m) break;                  // remaining candidates >= r^2 >= m
        int xl = w - r, xr = w + r;
        if (xl < 0 && xr >= Wn) break;
        if (xl >= 0) {
            int pk = sp[xl];
            float g = ((pk >> 20) == c) ? (float)(pk & 0xFFFFF) : 0.0f;
            m = fminf(m, g + r2);
        }
        if (xr < Wn) {
            int pk = sp[xr];
            float g = ((pk >> 20) == c) ? (float)(pk & 0xFFFFF) : 0.0f;
            m = fminf(m, g + r2);
        }
    }
    return m;
}

__global__ __launch_bounds__(TPB, 16)
void boundary_loss_kernel(const float* __restrict__ pred,
                          const int* __restrict__ mask,
                          float* __restrict__ out, int out_n) {
    __shared__ int s_pk[Wn];
    __shared__ float ws[TPB / 32];

    const int lane = threadIdx.x & 31;
    const int w0 = threadIdx.x * 2;            // two adjacent pixels w0, w0+1
    const int b = blockIdx.x >> 8;
    const int h = blockIdx.x & (Hn - 1);
    const int base = b * (Hn * Wn);
    const bool interior = (h >= 4) && (h <= Hn - 5);

    // ---- ONE load round: probe + 9-row int2 window + 3 float2 preds ----
    const int probe = __ldg(mask + 2 * lane + 1);
    int2 mv[9];                                // rows h-4 .. h+4, columns w0,w0+1
    const int2* mrow = (const int2*)(mask + base + w0);
    if (interior) {
#pragma unroll
        for (int i = 0; i < 9; ++i) mv[i] = __ldg(mrow + (h - 4 + i) * (Wn / 2));
    } else {
#pragma unroll
        for (int i = 0; i < 9; ++i) {
            int hr = h - 4 + i;
            hr = (hr < 0) ? 0 : ((hr > Hn - 1) ? Hn - 1 : hr);
            mv[i] = __ldg(mrow + hr * (Wn / 2));
        }
    }
    const float2* prow = (const float2*)(pred + b * Cn * Hn * Wn + h * Wn + w0);
    float2 pr[3];
#pragma unroll
    for (int k = 0; k < 3; ++k) pr[k] = __ldg(prow + (k + 1) * Hn * (Wn / 2));

    // int64 storage => all odd 32-bit words zero (fp prob 4^-32): reload.
    const int is64 = __all_sync(0xFFFFFFFFu, probe == 0) ? 1 : 0;
    if (is64) {
#pragma unroll
        for (int i = 0; i < 9; ++i) {
            int hr = h - 4 + i;
            hr = (hr < 0) ? 0 : ((hr > Hn - 1) ? Hn - 1 : hr);
            mv[i].x = __ldg(mask + 2 * (base + hr * Wn + w0));
            mv[i].y = __ldg(mask + 2 * (base + hr * Wn + w0 + 1));
        }
    }
    const int cA = mv[4].x;                    // pixel (h, w0)
    const int cB = mv[4].y;                    // pixel (h, w0+1)
    const float pA = (cA == 0) ? 0.0f : ((cA == 1) ? pr[0].x : (cA == 2) ? pr[1].x : pr[2].x);
    const float pB = (cB == 0) ? 0.0f : ((cB == 1) ? pr[0].y : (cB == 2) ? pr[1].y : pr[2].y);

    // ---- vertical distances (k<=4 from window, rare deep fallback) ----
    float g2A = 0.0f, g2B = 0.0f;
    int pkA = 0, pkB = 0;
    if (cA != 0) {
        int bits = 0;
        if (interior) {
#pragma unroll
            for (int j = 1; j <= 4; ++j)
                bits |= ((mv[4 - j].x != cA) | (mv[4 + j].x != cA)) << (j - 1);
        } else {
#pragma unroll
            for (int j = 1; j <= 4; ++j) {
                int uv = (j <= h) ? mv[4 - j].x : cA;
                int dv = (h + j < Hn) ? mv[4 + j].x : cA;
                bits |= ((uv != cA) | (dv != cA)) << (j - 1);
            }
        }
        int g0 = bits ? __ffs(bits) : deep_vdist(mask, base, h, w0, cA, is64);
        int gg = g0 * g0;
        g2A = (float)gg;
        pkA = (cA << 20) | gg;
    }
    if (cB != 0) {
        int bits = 0;
        if (interior) {
#pragma unroll
            for (int j = 1; j <= 4; ++j)
                bits |= ((mv[4 - j].y != cB) | (mv[4 + j].y != cB)) << (j - 1);
        } else {
#pragma unroll
            for (int j = 1; j <= 4; ++j) {
                int uv = (j <= h) ? mv[4 - j].y : cB;
                int dv = (h + j < Hn) ? mv[4 + j].y : cB;
                bits |= ((uv != cB) | (dv != cB)) << (j - 1);
            }
        }
        int g0 = bits ? __ffs(bits) : deep_vdist(mask, base, h, w0 + 1, cB, is64);
        int gg = g0 * g0;
        g2B = (float)gg;
        pkB = (cB << 20) | gg;
    }

    s_pk[w0] = pkA;
    s_pk[w0 + 1] = pkB;
    __syncthreads();

    // ---- exact horizontal lower envelopes (body skipped when m == 1) ----
    const float norm = (float)(sqrt((double)(Hn * Hn + Wn * Wn)) + 1e-6);
    float term = 0.0f;
    if (cA != 0) {
        float m = envelope(s_pk, w0, cA, g2A);
        term += pA * (sqrtf(m) / norm);
    }
    if (cB != 0) {
        float m = envelope(s_pk, w0 + 1, cB, g2B);
        term += pB * (sqrtf(m) / norm);
    }

    // ---- block reduction + single-accumulator finalize ----
#pragma unroll
    for (int o = 16; o > 0; o >>= 1)
        term += __shfl_down_sync(0xFFFFFFFFu, term, o);
    if (lane == 0) ws[threadIdx.x >> 5] = term;
    __syncthreads();
    if (threadIdx.x < TPB / 32) {
        float v = ws[threadIdx.x];
#pragma unroll
        for (int o = 2; o > 0; o >>= 1)
            v += __shfl_down_sync(0xFu, v, o);
        if (threadIdx.x == 0) {
            atomicAdd(&g_acc, (double)v);
            __threadfence();  // order my g_acc add before my g_count bump
            unsigned prev = atomicAdd(&g_count, 1u);
            if (prev == (unsigned)(gridDim.x - 1)) {
                double total = atomicAdd(&g_acc, 0.0);  // L2-coherent read
                float r = (float)(total / ((double)NPIX * (Cn - 1)));
                for (int i = 0; i < out_n; ++i) out[i] = r;
                g_acc = 0.0;   // reset for next graph replay (deterministic)
                g_count = 0u;
            }
        }
    }
}

extern "C" void kernel_launch(void* const* d_in, const int* in_sizes, int n_in,
                              void* d_out, int out_size) {
    const float* pred;
    const int* mask;
    if (in_sizes[0] >= in_sizes[1]) {
        pred = (const float*)d_in[0];
        mask = (const int*)d_in[1];
    } else {
        pred = (const float*)d_in[1];
        mask = (const int*)d_in[0];
    }
    boundary_loss_kernel<<<NBLK, TPB>>>(pred, mask, (float*)d_out, out_size);
}